// round 10
// baseline (speedup 1.0000x reference)
#include <cuda_runtime.h>
#include <cuda_fp16.h>
#include <math.h>

#define NGROUPS   4
#define NPERG     10
#define NFILT     40
#define TIME_LEN  64000
#define BATCH     32
#define POOLSZ    401
#define POOLSTR   160
#define OUT_T     400
#define MAX_WS    512
#define MAX_KH    480            // kstr max (kpad<=464 + 8)

// Scratch (static device globals — allowed; runtime alloc is not)
__device__ __half g_kernh[NGROUPS][24 * MAX_KH];   // B: [channel][tap], fp16, zero-padded
__device__ float  g_win  [NGROUPS][MAX_WS * NPERG];
__device__ __half g_mid  [4ll * BATCH * TIME_LEN * NPERG];

struct MetaAll {
    int a[4], cs[4], ps[4], k[4], ws[4], Tg[4], kpad[4], kstr[4];
    long long off[4];
};

// ---------------------------------------------------------------------------
// Precompute: B table fp16 [n][tap] (n = 2f + (0:cos,1:sin), padded to 24 ch,
// kstr taps) + fp32 pooling windows. Double precision trig.
// ---------------------------------------------------------------------------
__global__ void precompute_kernel(const float* __restrict__ cf_in,
                                  const float* __restrict__ bw_in,
                                  const float* __restrict__ pw_in,
                                  MetaAll meta) {
    const int g  = blockIdx.x;
    const int a  = meta.a[g];
    const int k  = meta.k[g];
    const int h  = k >> 1;
    const int ws = meta.ws[g];
    const int cs = meta.cs[g];
    const int kstr = meta.kstr[g];
    const double PI = 3.14159265358979323846;
    const double Zd = sqrt(2.0 * log(2.0)) / PI;

    const int stride = blockDim.x * gridDim.y;
    const int start0 = blockIdx.y * blockDim.x + threadIdx.x;

    for (int idx = start0; idx < 24 * kstr; idx += stride) {
        int n = idx / kstr, tt = idx % kstr;
        double v = 0.0;
        if (n < 20 && tt < k) {
            int f = n >> 1;
            bool is_sin = n & 1;
            float cff = fminf(fmaxf(cf_in[a + f], 0.f), (float)PI);
            float bwf = fminf(fmaxf(bw_in[a + f], (float)(2.0 * Zd)), (float)(401.0 * Zd));
            double t  = (double)(tt - h);
            double bw = (double)bwf;
            double gauss = exp(-t * t / (2.0 * bw * bw));
            double norm  = 1.0 / (sqrt(2.0 * PI) * bw);
            double ph    = t * (double)cff;
            v = norm * gauss * (is_sin ? sin(ph) : cos(ph));
        }
        g_kernh[g][n * kstr + tt] = __float2half_rn((float)v);
    }
    for (int idx = start0; idx < ws * 10; idx += stride) {
        int j = idx / 10, f = idx % 10;
        float pwf = fminf(fmaxf(pw_in[a + f], (float)(2.0 / 401.0)), 0.5f);
        double sigma = (double)pwf / (double)cs * 401.0 / (double)ws;
        double hw = 0.5 * (double)(ws - 1);
        double u  = ((double)j - hw) / (sigma * hw);
        g_win[g][idx] = (float)exp(-0.5 * u * u);
    }
}

// ---------------------------------------------------------------------------
// mma / ldmatrix primitives
// ---------------------------------------------------------------------------
__device__ __forceinline__ void mma16816(float* d,
        unsigned a0, unsigned a1, unsigned a2, unsigned a3,
        unsigned b0, unsigned b1) {
    asm("mma.sync.aligned.m16n8k16.row.col.f32.f16.f16.f32 "
        "{%0,%1,%2,%3}, {%4,%5,%6,%7}, {%8,%9}, {%0,%1,%2,%3};"
        : "+f"(d[0]), "+f"(d[1]), "+f"(d[2]), "+f"(d[3])
        : "r"(a0), "r"(a1), "r"(a2), "r"(a3), "r"(b0), "r"(b1));
}
__device__ __forceinline__ void ldsm4(unsigned& r0, unsigned& r1,
                                      unsigned& r2, unsigned& r3, unsigned addr) {
    asm volatile("ldmatrix.sync.aligned.m8n8.x4.shared.b16 {%0,%1,%2,%3}, [%4];"
                 : "=r"(r0), "=r"(r1), "=r"(r2), "=r"(r3) : "r"(addr));
}
__device__ __forceinline__ void ldsm2(unsigned& r0, unsigned& r1, unsigned addr) {
    asm volatile("ldmatrix.sync.aligned.m8n8.x2.shared.b16 {%0,%1}, [%2];"
                 : "=r"(r0), "=r"(r1) : "r"(addr));
}
__device__ __forceinline__ unsigned smem_u32(const void* p) {
    unsigned r;
    asm("{ .reg .u64 t; cvta.to.shared.u64 t, %1; cvt.u32.u64 %0, t; }"
        : "=r"(r) : "l"(p));
    return r;
}

// ---------------------------------------------------------------------------
// Conv as im2col GEMM with ldmatrix fragment loads.
// Block = 128 thr = 4 warps = 128 output rows; N = 24 channels.
// A rows are shifted views of x; 16B ldmatrix row alignment is achieved with
// NC = 8/gcd(CS,8) shift-copies of the x tile: row r reads copy (r*CS mod 8)/G
// at offset r*CS - (r*CS mod 8) + kk  (kk multiple of 16 halves -> 16B aligned).
// ---------------------------------------------------------------------------
template<int CS>
__global__ void __launch_bounds__(128) convmma(
        const float* __restrict__ x, int g, long long off,
        int kpad, int kstr, int Tg, int nxp) {
    constexpr int G  = (CS % 8 == 0) ? 8 : (CS % 4 == 0) ? 4 : (CS % 2 == 0) ? 2 : 1;
    constexpr int NC = 8 / G;

    extern __shared__ __align__(16) __half smh[];
    __half* Bsh = smh;                        // 24*kstr halves (kstr mult of 8)
    __half* Ash = Bsh + 24 * kstr;            // NC * nxp halves

    const int tid = threadIdx.x;
    {   // stage B table as u32
        const unsigned* s = (const unsigned*)&g_kernh[g][0];
        unsigned* dst = (unsigned*)Bsh;
        const int n32 = 24 * kstr / 2;
        for (int i = tid; i < n32; i += 128) dst[i] = s[i];
    }
    const int w0 = blockIdx.x * 128;
    const int b  = blockIdx.y;
    const int h  = (kpad > 16) ? ((kpad == 48) ? 20 : (kpad == 80) ? 35
                   : (kpad == 144) ? 71 : 143) : 0;   // placeholder; recomputed below
    // h passed implicitly via base: compute from k = 2h+1 not available here;
    // base uses half-window derived from kpad? NO — pass exact base via kstr trick.
    // (see base computation below using off-independent formula)
    const int nx = 128 * CS + kpad;
    const float* xb = x + (long long)b * TIME_LEN;
    // exact half-window: k = kpad - pad where pad makes kpad mult 16; we need h
    // exactly -> encode h in upper bits of nxp? Cleaner: h = (kpad_to_h passed via Tg? )
    // -> We pass h through 'nxp' lower 16 bits trick avoided; instead h is
    //    recoverable: host guarantees nxp = ((nx + 8 + 7) & ~7) | 0, and passes
    //    h separately packed in kstr? No. Simplest: h passed as its own param.
    (void)h;
    const int hh = (int)(off >> 48);          // h packed in top bits of off
    const long long off_lo = off & 0xFFFFFFFFFFFFll;
    const int base = w0 * CS - hh;
    for (int i = tid; i < NC * nxp; i += 128) {
        int ci = i / nxp, j = i % nxp;
        int gx = base + ci * G + j;
        Ash[i] = __float2half_rn(((unsigned)gx < (unsigned)TIME_LEN && j < nx)
                                  ? xb[gx] : 0.f);
    }
    __syncthreads();

    const int wid = tid >> 5, l = tid & 31;
    const int li = l & 7, quad = l >> 3;

    // ---- ldmatrix lane addresses (bytes, shared space) ----
    const unsigned smbase = smem_u32(smh);
    // A tiles: rows r = wid*32 + li + (quad&1)*8 (+16 for tile1), col (quad>>1)*8
    unsigned addrA0, addrA1;
    {
        int colq = (quad >> 1) * 8;
        int r0 = wid * 32 + li + (quad & 1) * 8;
        int rCS0 = r0 * CS;  int s0 = rCS0 & 7;
        addrA0 = smbase + (unsigned)(24 * kstr + (s0 / G) * nxp + rCS0 - s0 + colq) * 2u;
        int r1 = r0 + 16;
        int rCS1 = r1 * CS;  int s1 = rCS1 & 7;
        addrA1 = smbase + (unsigned)(24 * kstr + (s1 / G) * nxp + rCS1 - s1 + colq) * 2u;
    }
    // B x4: lanes 0-7 ch0-7@kk, 8-15 ch0-7@kk+8, 16-23 ch8-15@kk, 24-31 ch8-15@kk+8
    unsigned addrB4, addrB2;
    {
        int ch4 = (l >> 4) * 8 + li;
        int col4 = ((l >> 3) & 1) * 8;
        addrB4 = smbase + (unsigned)(ch4 * kstr + col4) * 2u;
        int l2 = l & 15;
        int ch2 = 16 + (l2 & 7);
        int col2 = ((l2 >> 3) & 1) * 8;
        addrB2 = smbase + (unsigned)(ch2 * kstr + col2) * 2u;
    }

    float d[2][3][4];
#pragma unroll
    for (int m2 = 0; m2 < 2; ++m2)
#pragma unroll
        for (int n = 0; n < 3; ++n)
#pragma unroll
            for (int e = 0; e < 4; ++e) d[m2][n][e] = 0.f;

#pragma unroll 2
    for (int kk = 0; kk < kpad; kk += 16) {
        unsigned a0, a1, a2, a3, c0, c1, c2, c3;
        unsigned b00, b01, b10, b11, b20, b21;
        ldsm4(a0, a1, a2, a3, addrA0);
        ldsm4(c0, c1, c2, c3, addrA1);
        ldsm4(b00, b01, b10, b11, addrB4);
        ldsm2(b20, b21, addrB2);
        addrA0 += 32; addrA1 += 32; addrB4 += 32; addrB2 += 32;
        mma16816(d[0][0], a0, a1, a2, a3, b00, b01);
        mma16816(d[0][1], a0, a1, a2, a3, b10, b11);
        mma16816(d[0][2], a0, a1, a2, a3, b20, b21);
        mma16816(d[1][0], c0, c1, c2, c3, b00, b01);
        mma16816(d[1][1], c0, c1, c2, c3, b10, b11);
        mma16816(d[1][2], c0, c1, c2, c3, b20, b21);
    }

    __half* mid = g_mid + off_lo;
    const int gq = l >> 2, t4 = l & 3;
    const long long rowbase = (long long)b * Tg + w0;
#pragma unroll
    for (int m2 = 0; m2 < 2; ++m2) {
        int ra = wid * 32 + gq + m2 * 16;
        int rb = ra + 8;
#pragma unroll
        for (int n = 0; n < 3; ++n) {
            int p = n * 4 + t4;
            if (p < 10) {
                float v0 = d[m2][n][0] * d[m2][n][0] + d[m2][n][1] * d[m2][n][1];
                float v1 = d[m2][n][2] * d[m2][n][2] + d[m2][n][3] * d[m2][n][3];
                mid[(rowbase + ra) * 10 + p] = __float2half_rn(v0);
                mid[(rowbase + rb) * 10 + p] = __float2half_rn(v1);
            }
        }
    }
}

// ---------------------------------------------------------------------------
// Merged depthwise Gaussian pooling: grid.y = group, one warp per (b, p).
// ---------------------------------------------------------------------------
__global__ void pool_kernel(float* __restrict__ out, MetaAll m) {
    const int g = blockIdx.y;
    const int ws = m.ws[g], ps = m.ps[g], Tg = m.Tg[g], a = m.a[g];
    const long long off = m.off[g];

    extern __shared__ float swin[];
    const float* wg = g_win[g];
    for (int i = threadIdx.x; i < ws * 10; i += blockDim.x) swin[i] = wg[i];
    __syncthreads();

    int warp = blockIdx.x * (blockDim.x >> 5) + (threadIdx.x >> 5);
    int lane = threadIdx.x & 31;
    if (warp >= BATCH * OUT_T) return;
    int p = warp % OUT_T;
    int b = warp / OUT_T;

    const __half* mrow = g_mid + off + (long long)b * Tg * 10;
    int t0 = p * ps - ws / 2;

    float2 acc2[5];
#pragma unroll
    for (int q = 0; q < 5; ++q) acc2[q] = make_float2(0.f, 0.f);

    for (int j = lane; j < ws; j += 32) {
        int t = t0 + j;
        if ((unsigned)t < (unsigned)Tg) {
            const __half2* row = (const __half2*)(mrow + (long long)t * 10);
            const float2* wr = (const float2*)(swin + j * 10);
#pragma unroll
            for (int q = 0; q < 5; ++q) {
                float2 rv = __half22float2(row[q]);
                float2 wv = wr[q];
                acc2[q].x = fmaf(wv.x, rv.x, acc2[q].x);
                acc2[q].y = fmaf(wv.y, rv.y, acc2[q].y);
            }
        }
    }

#pragma unroll
    for (int o = 16; o; o >>= 1)
#pragma unroll
        for (int q = 0; q < 5; ++q) {
            acc2[q].x += __shfl_down_sync(0xffffffffu, acc2[q].x, o);
            acc2[q].y += __shfl_down_sync(0xffffffffu, acc2[q].y, o);
        }

    if (lane == 0) {
        float* op = out + ((long long)b * OUT_T + p) * 40 + a;
#pragma unroll
        for (int q = 0; q < 5; ++q) {
            op[2*q]     = acc2[q].x;
            op[2*q + 1] = acc2[q].y;
        }
    }
}

// ---------------------------------------------------------------------------
// Host: replicate _mel_gabor_init + _group_meta exactly.
// ---------------------------------------------------------------------------
static void build_meta(MetaAll& m) {
    const double PI = 3.14159265358979323846;
    double freqs[257];
    for (int i = 0; i < 257; ++i) freqs[i] = 8000.0 * (double)i / 256.0;
    auto hz2mel = [](double f) { return 2595.0 * log10(1.0 + f / 700.0); };
    auto mel2hz = [](double mm) { return 700.0 * (pow(10.0, mm / 2595.0) - 1.0); };
    double mlo = hz2mel(60.0), mhi = hz2mel(7800.0);
    double hz[42];
    for (int i = 0; i < 42; ++i) hz[i] = mel2hz(mlo + (mhi - mlo) * (double)i / 41.0);

    const double Zd = sqrt(2.0 * log(2.0)) / PI;
    float cff[NFILT], bwf[NFILT];
    for (int i = 0; i < NFILT; ++i) {
        double l = hz[i], c = hz[i + 1], r = hz[i + 2];
        double peak = -1.0; int cb = 0;
        double vals[257];
        for (int j = 0; j < 257; ++j) {
            double v = (freqs[j] - l) / (c - l);
            double v2 = (r - freqs[j]) / (r - c);
            if (v2 < v) v = v2;
            if (v < 0.0) v = 0.0;
            vals[j] = sqrt(v);
            if (vals[j] > peak) { peak = vals[j]; cb = j; }
        }
        int fwhm = 0;
        for (int j = 0; j < 257; ++j) if (vals[j] >= 0.5 * peak) fwhm++;
        float cfv = (float)((double)cb * 2.0 * PI / 512.0);
        float bwv = (float)(sqrt(2.0 * log(2.0)) * 512.0 / (PI * (double)fwhm));
        cfv = fminf(fmaxf(cfv, 0.f), (float)PI);
        bwv = fminf(fmaxf(bwv, (float)(2.0 * Zd)), (float)(401.0 * Zd));
        cff[i] = cfv; bwf[i] = bwv;
    }

    const int divs[12] = {1, 2, 4, 5, 8, 10, 16, 20, 32, 40, 80, 160};
    long long off = 0;
    for (int g = 0; g < NGROUPS; ++g) {
        int a = g * NPERG, b = a + NPERG;
        float cmax = -1.f, bmax = -1.f;
        for (int i = a; i < b; ++i) {
            if (cff[i] > cmax) cmax = cff[i];
            if (bwf[i] > bmax) bmax = bwf[i];
        }
        double s = PI / (double)cmax;          // STRIDE_FACTOR = 1
        if (s < 1.0) s = 1.0;
        int cs = 1;
        for (int d = 0; d < 12; ++d) if ((double)divs[d] <= s) cs = divs[d];
        int k = (int)((double)bmax * 3.0);
        k += 1 - (k % 2);
        int ws = (int)(401.0 / (double)cs + 0.5);
        ws += 1 - (ws % 2);
        if (ws > MAX_WS - 1) ws = MAX_WS - 1;
        m.a[g] = a; m.cs[g] = cs; m.ps[g] = POOLSTR / cs;
        m.k[g] = k; m.ws[g] = ws; m.Tg[g] = TIME_LEN / cs;
        m.kpad[g] = ((k + 15) / 16) * 16;
        m.kstr[g] = m.kpad[g] + 8;             // multiple of 8 halves
        m.off[g] = off;
        off += (long long)BATCH * (TIME_LEN / cs) * NPERG;
    }
}

template<int CS>
static void launch_conv(const float* x, int g, const MetaAll& m) {
    const int G  = (CS % 8 == 0) ? 8 : (CS % 4 == 0) ? 4 : (CS % 2 == 0) ? 2 : 1;
    const int NC = 8 / G;
    int nx  = 128 * CS + m.kpad[g];
    int nxp = (nx + 8 + 7) & ~7;
    size_t smem = (size_t)(24 * m.kstr[g] + NC * nxp) * sizeof(__half);
    cudaFuncSetAttribute(convmma<CS>, cudaFuncAttributeMaxDynamicSharedMemorySize,
                         (int)smem);
    dim3 grid(m.Tg[g] / 128, BATCH);
    long long off_packed = m.off[g] | ((long long)(m.k[g] >> 1) << 48);
    convmma<CS><<<grid, 128, smem>>>(x, g, off_packed, m.kpad[g],
                                     m.kstr[g], m.Tg[g], nxp);
}

extern "C" void kernel_launch(void* const* d_in, const int* in_sizes, int n_in,
                              void* d_out, int out_size) {
    const float* x  = (const float*)d_in[0];
    const float* cf = (const float*)d_in[1];
    const float* bw = (const float*)d_in[2];
    const float* pw = (const float*)d_in[3];
    float* out = (float*)d_out;

    MetaAll m;
    build_meta(m);

    precompute_kernel<<<dim3(NGROUPS, 8), 256>>>(cf, bw, pw, m);

    for (int g = 0; g < NGROUPS; ++g) {
        switch (m.cs[g]) {
            case 1:  launch_conv<1 >(x, g, m); break;
            case 2:  launch_conv<2 >(x, g, m); break;
            case 4:  launch_conv<4 >(x, g, m); break;
            case 5:  launch_conv<5 >(x, g, m); break;
            case 8:  launch_conv<8 >(x, g, m); break;
            case 10: launch_conv<10>(x, g, m); break;
            case 16: launch_conv<16>(x, g, m); break;
            case 20: launch_conv<20>(x, g, m); break;
            case 32: launch_conv<32>(x, g, m); break;
            default: launch_conv<40>(x, g, m); break;
        }
    }

    size_t pool_smem = 0;
    for (int g = 0; g < NGROUPS; ++g) {
        size_t s = (size_t)(m.ws[g] * NPERG) * sizeof(float);
        if (s > pool_smem) pool_smem = s;
    }
    int pool_bx = (BATCH * OUT_T + 7) / 8;
    dim3 pool_grid(pool_bx, NGROUPS);
    pool_kernel<<<pool_grid, 256, pool_smem>>>(out, m);
}

// round 11
// speedup vs baseline: 1.1921x; 1.1921x over previous
#include <cuda_runtime.h>
#include <cuda_fp16.h>
#include <math.h>

#define NGROUPS   4
#define NPERG     10
#define NFILT     40
#define TIME_LEN  64000
#define BATCH     32
#define POOLSZ    401
#define POOLSTR   160
#define OUT_T     400
#define MAX_WS    512
#define MAX_KH    480            // kstr max (kpad<=464 + 8)
#define ROWS_B    256            // output rows per conv block (8 warps x 32)

// Scratch (static device globals — allowed; runtime alloc is not)
__device__ __half g_kernh[NGROUPS][24 * MAX_KH];   // B: [channel][tap], fp16, zero-padded
__device__ float  g_win  [NGROUPS][MAX_WS * NPERG];
__device__ __half g_mid  [4ll * BATCH * TIME_LEN * NPERG];

struct MetaAll {
    int a[4], cs[4], ps[4], k[4], ws[4], Tg[4], kpad[4], kstr[4];
    long long off[4];
};

// ---------------------------------------------------------------------------
// Precompute: B table fp16 [n][tap] (n = 2f + (0:cos,1:sin), padded to 24 ch,
// kstr taps) + fp32 pooling windows. Double precision trig.
// ---------------------------------------------------------------------------
__global__ void precompute_kernel(const float* __restrict__ cf_in,
                                  const float* __restrict__ bw_in,
                                  const float* __restrict__ pw_in,
                                  MetaAll meta) {
    const int g  = blockIdx.x;
    const int a  = meta.a[g];
    const int k  = meta.k[g];
    const int h  = k >> 1;
    const int ws = meta.ws[g];
    const int cs = meta.cs[g];
    const int kstr = meta.kstr[g];
    const double PI = 3.14159265358979323846;
    const double Zd = sqrt(2.0 * log(2.0)) / PI;

    const int stride = blockDim.x * gridDim.y;
    const int start0 = blockIdx.y * blockDim.x + threadIdx.x;

    for (int idx = start0; idx < 24 * kstr; idx += stride) {
        int n = idx / kstr, tt = idx % kstr;
        double v = 0.0;
        if (n < 20 && tt < k) {
            int f = n >> 1;
            bool is_sin = n & 1;
            float cff = fminf(fmaxf(cf_in[a + f], 0.f), (float)PI);
            float bwf = fminf(fmaxf(bw_in[a + f], (float)(2.0 * Zd)), (float)(401.0 * Zd));
            double t  = (double)(tt - h);
            double bw = (double)bwf;
            double gauss = exp(-t * t / (2.0 * bw * bw));
            double norm  = 1.0 / (sqrt(2.0 * PI) * bw);
            double ph    = t * (double)cff;
            v = norm * gauss * (is_sin ? sin(ph) : cos(ph));
        }
        g_kernh[g][n * kstr + tt] = __float2half_rn((float)v);
    }
    for (int idx = start0; idx < ws * 10; idx += stride) {
        int j = idx / 10, f = idx % 10;
        float pwf = fminf(fmaxf(pw_in[a + f], (float)(2.0 / 401.0)), 0.5f);
        double sigma = (double)pwf / (double)cs * 401.0 / (double)ws;
        double hw = 0.5 * (double)(ws - 1);
        double u  = ((double)j - hw) / (sigma * hw);
        g_win[g][idx] = (float)exp(-0.5 * u * u);
    }
}

// ---------------------------------------------------------------------------
// mma.sync m16n8k16 fp16 -> fp32 (HMMA)
// ---------------------------------------------------------------------------
__device__ __forceinline__ void mma16816(float* d,
        unsigned a0, unsigned a1, unsigned a2, unsigned a3,
        unsigned b0, unsigned b1) {
    asm("mma.sync.aligned.m16n8k16.row.col.f32.f16.f16.f32 "
        "{%0,%1,%2,%3}, {%4,%5,%6,%7}, {%8,%9}, {%0,%1,%2,%3};"
        : "+f"(d[0]), "+f"(d[1]), "+f"(d[2]), "+f"(d[3])
        : "r"(a0), "r"(a1), "r"(a2), "r"(a3), "r"(b0), "r"(b1));
}

// ---------------------------------------------------------------------------
// Conv as im2col GEMM (R9 fragment scheme), 8 warps / 256 rows per block,
// 2-step software-pipelined mainloop (two fragment sets in flight).
// ---------------------------------------------------------------------------
template<int CS>
__global__ void __launch_bounds__(256) convmma(
        const float* __restrict__ x, int g, long long off,
        int k, int kpad, int kstr, int Tg) {
    extern __shared__ __align__(16) __half smh[];
    __half* Bsh = smh;                       // 24*kstr halves
    const int nx = ROWS_B * CS + kpad;
    __half* xsh  = Bsh + 24 * kstr;          // nx+2 halves
    __half* xsh2 = xsh + nx + 2;             // odd-CS shifted copy

    const int tid = threadIdx.x;
    {   // stage B table as u32
        const unsigned* s = (const unsigned*)&g_kernh[g][0];
        unsigned* dst = (unsigned*)Bsh;
        const int n32 = 24 * kstr / 2;
        for (int i = tid; i < n32; i += 256) dst[i] = s[i];
    }
    const int w0 = blockIdx.x * ROWS_B;
    const int b  = blockIdx.y;
    const int h  = k >> 1;
    const int base = w0 * CS - h;
    const float* xb = x + (long long)b * TIME_LEN;
    for (int i = tid; i < nx; i += 256) {
        int gx = base + i;
        xsh[i] = __float2half_rn(((unsigned)gx < (unsigned)TIME_LEN) ? xb[gx] : 0.f);
        if (CS & 1) {
            int gx2 = gx + 1;
            xsh2[i] = __float2half_rn(((unsigned)gx2 < (unsigned)TIME_LEN) ? xb[gx2] : 0.f);
        }
    }
    __syncthreads();

    const int wid = tid >> 5, l = tid & 31, gq = l >> 2, t4 = l & 3;
    const int cb = 2 * t4;

    // per-row base pointer + half-offset (parity-corrected for odd CS)
    const __half* pr[4]; int orw[4];
#pragma unroll
    for (int j = 0; j < 4; ++j) {
        int r = wid * 32 + gq + j * 8;
        int o = r * CS;
        if ((CS & 1) && (o & 1)) { pr[j] = xsh2; orw[j] = o - 1; }
        else                     { pr[j] = xsh;  orw[j] = o;     }
    }
    const __half* q0 = Bsh + gq * kstr;
    const __half* q1 = Bsh + (8  + gq) * kstr;
    const __half* q2 = Bsh + (16 + gq) * kstr;

    float d[2][3][4];
#pragma unroll
    for (int m2 = 0; m2 < 2; ++m2)
#pragma unroll
        for (int n = 0; n < 3; ++n)
#pragma unroll
            for (int e = 0; e < 4; ++e) d[m2][n][e] = 0.f;

    // fragment loaders
    auto loadA = [&](int o, unsigned* A, unsigned* C) {
        A[0] = *(const unsigned*)(pr[0] + orw[0] + o);
        A[1] = *(const unsigned*)(pr[1] + orw[1] + o);
        A[2] = *(const unsigned*)(pr[0] + orw[0] + o + 8);
        A[3] = *(const unsigned*)(pr[1] + orw[1] + o + 8);
        C[0] = *(const unsigned*)(pr[2] + orw[2] + o);
        C[1] = *(const unsigned*)(pr[3] + orw[3] + o);
        C[2] = *(const unsigned*)(pr[2] + orw[2] + o + 8);
        C[3] = *(const unsigned*)(pr[3] + orw[3] + o + 8);
    };
    auto loadB = [&](int o, unsigned* B) {
        B[0] = *(const unsigned*)(q0 + o); B[1] = *(const unsigned*)(q0 + o + 8);
        B[2] = *(const unsigned*)(q1 + o); B[3] = *(const unsigned*)(q1 + o + 8);
        B[4] = *(const unsigned*)(q2 + o); B[5] = *(const unsigned*)(q2 + o + 8);
    };
    auto mma6 = [&](const unsigned* A, const unsigned* C, const unsigned* B) {
        mma16816(d[0][0], A[0], A[1], A[2], A[3], B[0], B[1]);
        mma16816(d[0][1], A[0], A[1], A[2], A[3], B[2], B[3]);
        mma16816(d[0][2], A[0], A[1], A[2], A[3], B[4], B[5]);
        mma16816(d[1][0], C[0], C[1], C[2], C[3], B[0], B[1]);
        mma16816(d[1][1], C[0], C[1], C[2], C[3], B[2], B[3]);
        mma16816(d[1][2], C[0], C[1], C[2], C[3], B[4], B[5]);
    };

    // 2-step pipelined mainloop: both fragment sets issued before consuming
    unsigned A0[4], C0[4], B0[6], A1[4], C1[4], B1[6];
    int kk = 0;
    for (; kk + 32 <= kpad; kk += 32) {
        loadA(kk + cb, A0, C0);       loadB(kk + cb, B0);
        loadA(kk + 16 + cb, A1, C1);  loadB(kk + 16 + cb, B1);
        mma6(A0, C0, B0);
        mma6(A1, C1, B1);
    }
    if (kk < kpad) {
        loadA(kk + cb, A0, C0);  loadB(kk + cb, B0);
        mma6(A0, C0, B0);
    }

    __half* mid = g_mid + off;
    const long long rowbase = (long long)b * Tg + w0;
#pragma unroll
    for (int m2 = 0; m2 < 2; ++m2) {
        int ra = wid * 32 + gq + m2 * 16;
        int rb = ra + 8;
#pragma unroll
        for (int n = 0; n < 3; ++n) {
            int p = n * 4 + t4;
            if (p < 10) {
                float v0 = d[m2][n][0] * d[m2][n][0] + d[m2][n][1] * d[m2][n][1];
                float v1 = d[m2][n][2] * d[m2][n][2] + d[m2][n][3] * d[m2][n][3];
                if (w0 + ra < Tg)
                    mid[(rowbase + ra) * 10 + p] = __float2half_rn(v0);
                if (w0 + rb < Tg)
                    mid[(rowbase + rb) * 10 + p] = __float2half_rn(v1);
            }
        }
    }
}

// ---------------------------------------------------------------------------
// Merged depthwise Gaussian pooling: grid.y = group, one warp per (b, p).
// ---------------------------------------------------------------------------
__global__ void pool_kernel(float* __restrict__ out, MetaAll m) {
    const int g = blockIdx.y;
    const int ws = m.ws[g], ps = m.ps[g], Tg = m.Tg[g], a = m.a[g];
    const long long off = m.off[g];

    extern __shared__ float swin[];
    const float* wg = g_win[g];
    for (int i = threadIdx.x; i < ws * 10; i += blockDim.x) swin[i] = wg[i];
    __syncthreads();

    int warp = blockIdx.x * (blockDim.x >> 5) + (threadIdx.x >> 5);
    int lane = threadIdx.x & 31;
    if (warp >= BATCH * OUT_T) return;
    int p = warp % OUT_T;
    int b = warp / OUT_T;

    const __half* mrow = g_mid + off + (long long)b * Tg * 10;
    int t0 = p * ps - ws / 2;

    float2 acc2[5];
#pragma unroll
    for (int q = 0; q < 5; ++q) acc2[q] = make_float2(0.f, 0.f);

    for (int j = lane; j < ws; j += 32) {
        int t = t0 + j;
        if ((unsigned)t < (unsigned)Tg) {
            const __half2* row = (const __half2*)(mrow + (long long)t * 10);
            const float2* wr = (const float2*)(swin + j * 10);
#pragma unroll
            for (int q = 0; q < 5; ++q) {
                float2 rv = __half22float2(row[q]);
                float2 wv = wr[q];
                acc2[q].x = fmaf(wv.x, rv.x, acc2[q].x);
                acc2[q].y = fmaf(wv.y, rv.y, acc2[q].y);
            }
        }
    }

#pragma unroll
    for (int o = 16; o; o >>= 1)
#pragma unroll
        for (int q = 0; q < 5; ++q) {
            acc2[q].x += __shfl_down_sync(0xffffffffu, acc2[q].x, o);
            acc2[q].y += __shfl_down_sync(0xffffffffu, acc2[q].y, o);
        }

    if (lane == 0) {
        float* op = out + ((long long)b * OUT_T + p) * 40 + a;
#pragma unroll
        for (int q = 0; q < 5; ++q) {
            op[2*q]     = acc2[q].x;
            op[2*q + 1] = acc2[q].y;
        }
    }
}

// ---------------------------------------------------------------------------
// Host: replicate _mel_gabor_init + _group_meta exactly.
// ---------------------------------------------------------------------------
static void build_meta(MetaAll& m) {
    const double PI = 3.14159265358979323846;
    double freqs[257];
    for (int i = 0; i < 257; ++i) freqs[i] = 8000.0 * (double)i / 256.0;
    auto hz2mel = [](double f) { return 2595.0 * log10(1.0 + f / 700.0); };
    auto mel2hz = [](double mm) { return 700.0 * (pow(10.0, mm / 2595.0) - 1.0); };
    double mlo = hz2mel(60.0), mhi = hz2mel(7800.0);
    double hz[42];
    for (int i = 0; i < 42; ++i) hz[i] = mel2hz(mlo + (mhi - mlo) * (double)i / 41.0);

    const double Zd = sqrt(2.0 * log(2.0)) / PI;
    float cff[NFILT], bwf[NFILT];
    for (int i = 0; i < NFILT; ++i) {
        double l = hz[i], c = hz[i + 1], r = hz[i + 2];
        double peak = -1.0; int cb = 0;
        double vals[257];
        for (int j = 0; j < 257; ++j) {
            double v = (freqs[j] - l) / (c - l);
            double v2 = (r - freqs[j]) / (r - c);
            if (v2 < v) v = v2;
            if (v < 0.0) v = 0.0;
            vals[j] = sqrt(v);
            if (vals[j] > peak) { peak = vals[j]; cb = j; }
        }
        int fwhm = 0;
        for (int j = 0; j < 257; ++j) if (vals[j] >= 0.5 * peak) fwhm++;
        float cfv = (float)((double)cb * 2.0 * PI / 512.0);
        float bwv = (float)(sqrt(2.0 * log(2.0)) * 512.0 / (PI * (double)fwhm));
        cfv = fminf(fmaxf(cfv, 0.f), (float)PI);
        bwv = fminf(fmaxf(bwv, (float)(2.0 * Zd)), (float)(401.0 * Zd));
        cff[i] = cfv; bwf[i] = bwv;
    }

    const int divs[12] = {1, 2, 4, 5, 8, 10, 16, 20, 32, 40, 80, 160};
    long long off = 0;
    for (int g = 0; g < NGROUPS; ++g) {
        int a = g * NPERG, b = a + NPERG;
        float cmax = -1.f, bmax = -1.f;
        for (int i = a; i < b; ++i) {
            if (cff[i] > cmax) cmax = cff[i];
            if (bwf[i] > bmax) bmax = bwf[i];
        }
        double s = PI / (double)cmax;          // STRIDE_FACTOR = 1
        if (s < 1.0) s = 1.0;
        int cs = 1;
        for (int d = 0; d < 12; ++d) if ((double)divs[d] <= s) cs = divs[d];
        int k = (int)((double)bmax * 3.0);
        k += 1 - (k % 2);
        int ws = (int)(401.0 / (double)cs + 0.5);
        ws += 1 - (ws % 2);
        if (ws > MAX_WS - 1) ws = MAX_WS - 1;
        m.a[g] = a; m.cs[g] = cs; m.ps[g] = POOLSTR / cs;
        m.k[g] = k; m.ws[g] = ws; m.Tg[g] = TIME_LEN / cs;
        m.kpad[g] = ((k + 15) / 16) * 16;
        m.kstr[g] = m.kpad[g] + 8;             // bank-spread row stride
        m.off[g] = off;
        off += (long long)BATCH * (TIME_LEN / cs) * NPERG;
    }
}

template<int CS>
static void launch_conv(const float* x, int g, const MetaAll& m) {
    int nx = ROWS_B * CS + m.kpad[g];
    size_t smem = (size_t)(24 * m.kstr[g] + (nx + 2) * ((CS & 1) ? 2 : 1))
                  * sizeof(__half);
    cudaFuncSetAttribute(convmma<CS>, cudaFuncAttributeMaxDynamicSharedMemorySize,
                         (int)smem);
    dim3 grid((m.Tg[g] + ROWS_B - 1) / ROWS_B, BATCH);
    convmma<CS><<<grid, 256, smem>>>(x, g, m.off[g], m.k[g], m.kpad[g],
                                     m.kstr[g], m.Tg[g]);
}

extern "C" void kernel_launch(void* const* d_in, const int* in_sizes, int n_in,
                              void* d_out, int out_size) {
    const float* x  = (const float*)d_in[0];
    const float* cf = (const float*)d_in[1];
    const float* bw = (const float*)d_in[2];
    const float* pw = (const float*)d_in[3];
    float* out = (float*)d_out;

    MetaAll m;
    build_meta(m);

    precompute_kernel<<<dim3(NGROUPS, 8), 256>>>(cf, bw, pw, m);

    for (int g = 0; g < NGROUPS; ++g) {
        switch (m.cs[g]) {
            case 1:  launch_conv<1 >(x, g, m); break;
            case 2:  launch_conv<2 >(x, g, m); break;
            case 4:  launch_conv<4 >(x, g, m); break;
            case 5:  launch_conv<5 >(x, g, m); break;
            case 8:  launch_conv<8 >(x, g, m); break;
            case 10: launch_conv<10>(x, g, m); break;
            case 16: launch_conv<16>(x, g, m); break;
            case 20: launch_conv<20>(x, g, m); break;
            case 32: launch_conv<32>(x, g, m); break;
            default: launch_conv<40>(x, g, m); break;
        }
    }

    size_t pool_smem = 0;
    for (int g = 0; g < NGROUPS; ++g) {
        size_t s = (size_t)(m.ws[g] * NPERG) * sizeof(float);
        if (s > pool_smem) pool_smem = s;
    }
    int pool_bx = (BATCH * OUT_T + 7) / 8;
    dim3 pool_grid(pool_bx, NGROUPS);
    pool_kernel<<<pool_grid, 256, pool_smem>>>(out, m);
}

// round 12
// speedup vs baseline: 1.3297x; 1.1154x over previous
#include <cuda_runtime.h>
#include <cuda_fp16.h>
#include <math.h>

#define NGROUPS   4
#define NPERG     10
#define NFILT     40
#define TIME_LEN  64000
#define BATCH     32
#define POOLSZ    401
#define POOLSTR   160
#define OUT_T     400
#define MAX_WS    512
#define MAX_KH    480            // kstr max (kpad<=464 + 8)
#define ROWS_B    256            // output rows per conv block (4 warps x 64)

// Scratch (static device globals — allowed; runtime alloc is not)
__device__ __half g_kernh[NGROUPS][24 * MAX_KH];   // B: [channel][tap], fp16, zero-padded
__device__ float  g_win  [NGROUPS][MAX_WS * NPERG];
__device__ __half g_mid  [4ll * BATCH * TIME_LEN * NPERG];

struct MetaAll {
    int a[4], cs[4], ps[4], k[4], ws[4], Tg[4], kpad[4], kstr[4];
    long long off[4];
};

// ---------------------------------------------------------------------------
// Precompute: B table fp16 [n][tap] (n = 2f + (0:cos,1:sin), padded to 24 ch,
// kstr taps) + fp32 pooling windows. Double precision trig.
// ---------------------------------------------------------------------------
__global__ void precompute_kernel(const float* __restrict__ cf_in,
                                  const float* __restrict__ bw_in,
                                  const float* __restrict__ pw_in,
                                  MetaAll meta) {
    const int g  = blockIdx.x;
    const int a  = meta.a[g];
    const int k  = meta.k[g];
    const int h  = k >> 1;
    const int ws = meta.ws[g];
    const int cs = meta.cs[g];
    const int kstr = meta.kstr[g];
    const double PI = 3.14159265358979323846;
    const double Zd = sqrt(2.0 * log(2.0)) / PI;

    const int stride = blockDim.x * gridDim.y;
    const int start0 = blockIdx.y * blockDim.x + threadIdx.x;

    for (int idx = start0; idx < 24 * kstr; idx += stride) {
        int n = idx / kstr, tt = idx % kstr;
        double v = 0.0;
        if (n < 20 && tt < k) {
            int f = n >> 1;
            bool is_sin = n & 1;
            float cff = fminf(fmaxf(cf_in[a + f], 0.f), (float)PI);
            float bwf = fminf(fmaxf(bw_in[a + f], (float)(2.0 * Zd)), (float)(401.0 * Zd));
            double t  = (double)(tt - h);
            double bw = (double)bwf;
            double gauss = exp(-t * t / (2.0 * bw * bw));
            double norm  = 1.0 / (sqrt(2.0 * PI) * bw);
            double ph    = t * (double)cff;
            v = norm * gauss * (is_sin ? sin(ph) : cos(ph));
        }
        g_kernh[g][n * kstr + tt] = __float2half_rn((float)v);
    }
    for (int idx = start0; idx < ws * 10; idx += stride) {
        int j = idx / 10, f = idx % 10;
        float pwf = fminf(fmaxf(pw_in[a + f], (float)(2.0 / 401.0)), 0.5f);
        double sigma = (double)pwf / (double)cs * 401.0 / (double)ws;
        double hw = 0.5 * (double)(ws - 1);
        double u  = ((double)j - hw) / (sigma * hw);
        g_win[g][idx] = (float)exp(-0.5 * u * u);
    }
}

// ---------------------------------------------------------------------------
// mma.sync m16n8k16 fp16 -> fp32 (HMMA)
// ---------------------------------------------------------------------------
__device__ __forceinline__ void mma16816(float* d,
        unsigned a0, unsigned a1, unsigned a2, unsigned a3,
        unsigned b0, unsigned b1) {
    asm("mma.sync.aligned.m16n8k16.row.col.f32.f16.f16.f32 "
        "{%0,%1,%2,%3}, {%4,%5,%6,%7}, {%8,%9}, {%0,%1,%2,%3};"
        : "+f"(d[0]), "+f"(d[1]), "+f"(d[2]), "+f"(d[3])
        : "r"(a0), "r"(a1), "r"(a2), "r"(a3), "r"(b0), "r"(b1));
}

// ---------------------------------------------------------------------------
// Conv as im2col GEMM (R9 fragment scheme), 128 threads / 4 warps,
// each warp owns 4 m16 tiles (64 rows) -> B fragment loads amortized 4x.
// ---------------------------------------------------------------------------
template<int CS>
__global__ void __launch_bounds__(128) convmma(
        const float* __restrict__ x, int g, long long off,
        int k, int kpad, int kstr, int Tg) {
    extern __shared__ __align__(16) __half smh[];
    __half* Bsh = smh;                       // 24*kstr halves
    const int nx = ROWS_B * CS + kpad;
    __half* xsh  = Bsh + 24 * kstr;          // nx+2 halves
    __half* xsh2 = xsh + nx + 2;             // odd-CS shifted copy

    const int tid = threadIdx.x;
    {   // stage B table as u32
        const unsigned* s = (const unsigned*)&g_kernh[g][0];
        unsigned* dst = (unsigned*)Bsh;
        const int n32 = 24 * kstr / 2;
        for (int i = tid; i < n32; i += 128) dst[i] = s[i];
    }
    const int w0 = blockIdx.x * ROWS_B;
    const int b  = blockIdx.y;
    const int h  = k >> 1;
    const int base = w0 * CS - h;
    const float* xb = x + (long long)b * TIME_LEN;
    for (int i = tid; i < nx; i += 128) {
        int gx = base + i;
        xsh[i] = __float2half_rn(((unsigned)gx < (unsigned)TIME_LEN) ? xb[gx] : 0.f);
        if (CS & 1) {
            int gx2 = gx + 1;
            xsh2[i] = __float2half_rn(((unsigned)gx2 < (unsigned)TIME_LEN) ? xb[gx2] : 0.f);
        }
    }
    __syncthreads();

    const int wid = tid >> 5, l = tid & 31, gq = l >> 2, t4 = l & 3;
    const int cb = 2 * t4;

    // per-fragment-row shared pointers (rows: wid*64 + mt*16 + gq (+8)),
    // parity-corrected for odd CS
    const __half* qr[8];
#pragma unroll
    for (int mt = 0; mt < 4; ++mt) {
#pragma unroll
        for (int jj = 0; jj < 2; ++jj) {
            int r = wid * 64 + mt * 16 + gq + jj * 8;
            int o = r * CS;
            if ((CS & 1) && (o & 1)) qr[mt * 2 + jj] = xsh2 + (o - 1);
            else                     qr[mt * 2 + jj] = xsh + o;
        }
    }
    const __half* q0 = Bsh + gq * kstr;
    const __half* q1 = Bsh + (8  + gq) * kstr;
    const __half* q2 = Bsh + (16 + gq) * kstr;

    float d[4][3][4];
#pragma unroll
    for (int mt = 0; mt < 4; ++mt)
#pragma unroll
        for (int n = 0; n < 3; ++n)
#pragma unroll
            for (int e = 0; e < 4; ++e) d[mt][n][e] = 0.f;

    for (int kk = 0; kk < kpad; kk += 16) {
        const int o = kk + cb;
        unsigned b00 = *(const unsigned*)(q0 + o), b01 = *(const unsigned*)(q0 + o + 8);
        unsigned b10 = *(const unsigned*)(q1 + o), b11 = *(const unsigned*)(q1 + o + 8);
        unsigned b20 = *(const unsigned*)(q2 + o), b21 = *(const unsigned*)(q2 + o + 8);
#pragma unroll
        for (int mt = 0; mt < 4; ++mt) {
            unsigned a0 = *(const unsigned*)(qr[mt * 2 + 0] + o);
            unsigned a1 = *(const unsigned*)(qr[mt * 2 + 1] + o);
            unsigned a2 = *(const unsigned*)(qr[mt * 2 + 0] + o + 8);
            unsigned a3 = *(const unsigned*)(qr[mt * 2 + 1] + o + 8);
            mma16816(d[mt][0], a0, a1, a2, a3, b00, b01);
            mma16816(d[mt][1], a0, a1, a2, a3, b10, b11);
            mma16816(d[mt][2], a0, a1, a2, a3, b20, b21);
        }
    }

    __half* mid = g_mid + off;
    const long long rowbase = (long long)b * Tg + w0;
#pragma unroll
    for (int mt = 0; mt < 4; ++mt) {
        int ra = wid * 64 + mt * 16 + gq;
        int rb = ra + 8;
#pragma unroll
        for (int n = 0; n < 3; ++n) {
            int p = n * 4 + t4;
            if (p < 10) {
                float v0 = d[mt][n][0] * d[mt][n][0] + d[mt][n][1] * d[mt][n][1];
                float v1 = d[mt][n][2] * d[mt][n][2] + d[mt][n][3] * d[mt][n][3];
                if (w0 + ra < Tg)
                    mid[(rowbase + ra) * 10 + p] = __float2half_rn(v0);
                if (w0 + rb < Tg)
                    mid[(rowbase + rb) * 10 + p] = __float2half_rn(v1);
            }
        }
    }
}

// ---------------------------------------------------------------------------
// Merged depthwise Gaussian pooling: grid.y = group, one warp per (b, p).
// ---------------------------------------------------------------------------
__global__ void pool_kernel(float* __restrict__ out, MetaAll m) {
    const int g = blockIdx.y;
    const int ws = m.ws[g], ps = m.ps[g], Tg = m.Tg[g], a = m.a[g];
    const long long off = m.off[g];

    extern __shared__ float swin[];
    const float* wg = g_win[g];
    for (int i = threadIdx.x; i < ws * 10; i += blockDim.x) swin[i] = wg[i];
    __syncthreads();

    int warp = blockIdx.x * (blockDim.x >> 5) + (threadIdx.x >> 5);
    int lane = threadIdx.x & 31;
    if (warp >= BATCH * OUT_T) return;
    int p = warp % OUT_T;
    int b = warp / OUT_T;

    const __half* mrow = g_mid + off + (long long)b * Tg * 10;
    int t0 = p * ps - ws / 2;

    float2 acc2[5];
#pragma unroll
    for (int q = 0; q < 5; ++q) acc2[q] = make_float2(0.f, 0.f);

    for (int j = lane; j < ws; j += 32) {
        int t = t0 + j;
        if ((unsigned)t < (unsigned)Tg) {
            const __half2* row = (const __half2*)(mrow + (long long)t * 10);
            const float2* wr = (const float2*)(swin + j * 10);
#pragma unroll
            for (int q = 0; q < 5; ++q) {
                float2 rv = __half22float2(row[q]);
                float2 wv = wr[q];
                acc2[q].x = fmaf(wv.x, rv.x, acc2[q].x);
                acc2[q].y = fmaf(wv.y, rv.y, acc2[q].y);
            }
        }
    }

#pragma unroll
    for (int o = 16; o; o >>= 1)
#pragma unroll
        for (int q = 0; q < 5; ++q) {
            acc2[q].x += __shfl_down_sync(0xffffffffu, acc2[q].x, o);
            acc2[q].y += __shfl_down_sync(0xffffffffu, acc2[q].y, o);
        }

    if (lane == 0) {
        float* op = out + ((long long)b * OUT_T + p) * 40 + a;
#pragma unroll
        for (int q = 0; q < 5; ++q) {
            op[2*q]     = acc2[q].x;
            op[2*q + 1] = acc2[q].y;
        }
    }
}

// ---------------------------------------------------------------------------
// Host: replicate _mel_gabor_init + _group_meta exactly.
// ---------------------------------------------------------------------------
static void build_meta(MetaAll& m) {
    const double PI = 3.14159265358979323846;
    double freqs[257];
    for (int i = 0; i < 257; ++i) freqs[i] = 8000.0 * (double)i / 256.0;
    auto hz2mel = [](double f) { return 2595.0 * log10(1.0 + f / 700.0); };
    auto mel2hz = [](double mm) { return 700.0 * (pow(10.0, mm / 2595.0) - 1.0); };
    double mlo = hz2mel(60.0), mhi = hz2mel(7800.0);
    double hz[42];
    for (int i = 0; i < 42; ++i) hz[i] = mel2hz(mlo + (mhi - mlo) * (double)i / 41.0);

    const double Zd = sqrt(2.0 * log(2.0)) / PI;
    float cff[NFILT], bwf[NFILT];
    for (int i = 0; i < NFILT; ++i) {
        double l = hz[i], c = hz[i + 1], r = hz[i + 2];
        double peak = -1.0; int cb = 0;
        double vals[257];
        for (int j = 0; j < 257; ++j) {
            double v = (freqs[j] - l) / (c - l);
            double v2 = (r - freqs[j]) / (r - c);
            if (v2 < v) v = v2;
            if (v < 0.0) v = 0.0;
            vals[j] = sqrt(v);
            if (vals[j] > peak) { peak = vals[j]; cb = j; }
        }
        int fwhm = 0;
        for (int j = 0; j < 257; ++j) if (vals[j] >= 0.5 * peak) fwhm++;
        float cfv = (float)((double)cb * 2.0 * PI / 512.0);
        float bwv = (float)(sqrt(2.0 * log(2.0)) * 512.0 / (PI * (double)fwhm));
        cfv = fminf(fmaxf(cfv, 0.f), (float)PI);
        bwv = fminf(fmaxf(bwv, (float)(2.0 * Zd)), (float)(401.0 * Zd));
        cff[i] = cfv; bwf[i] = bwv;
    }

    const int divs[12] = {1, 2, 4, 5, 8, 10, 16, 20, 32, 40, 80, 160};
    long long off = 0;
    for (int g = 0; g < NGROUPS; ++g) {
        int a = g * NPERG, b = a + NPERG;
        float cmax = -1.f, bmax = -1.f;
        for (int i = a; i < b; ++i) {
            if (cff[i] > cmax) cmax = cff[i];
            if (bwf[i] > bmax) bmax = bwf[i];
        }
        double s = PI / (double)cmax;          // STRIDE_FACTOR = 1
        if (s < 1.0) s = 1.0;
        int cs = 1;
        for (int d = 0; d < 12; ++d) if ((double)divs[d] <= s) cs = divs[d];
        int k = (int)((double)bmax * 3.0);
        k += 1 - (k % 2);
        int ws = (int)(401.0 / (double)cs + 0.5);
        ws += 1 - (ws % 2);
        if (ws > MAX_WS - 1) ws = MAX_WS - 1;
        m.a[g] = a; m.cs[g] = cs; m.ps[g] = POOLSTR / cs;
        m.k[g] = k; m.ws[g] = ws; m.Tg[g] = TIME_LEN / cs;
        m.kpad[g] = ((k + 15) / 16) * 16;
        m.kstr[g] = m.kpad[g] + 8;             // bank-spread row stride
        m.off[g] = off;
        off += (long long)BATCH * (TIME_LEN / cs) * NPERG;
    }
}

template<int CS>
static void launch_conv(const float* x, int g, const MetaAll& m) {
    int nx = ROWS_B * CS + m.kpad[g];
    size_t smem = (size_t)(24 * m.kstr[g] + (nx + 2) * ((CS & 1) ? 2 : 1))
                  * sizeof(__half);
    cudaFuncSetAttribute(convmma<CS>, cudaFuncAttributeMaxDynamicSharedMemorySize,
                         (int)smem);
    dim3 grid((m.Tg[g] + ROWS_B - 1) / ROWS_B, BATCH);
    convmma<CS><<<grid, 128, smem>>>(x, g, m.off[g], m.k[g], m.kpad[g],
                                     m.kstr[g], m.Tg[g]);
}

extern "C" void kernel_launch(void* const* d_in, const int* in_sizes, int n_in,
                              void* d_out, int out_size) {
    const float* x  = (const float*)d_in[0];
    const float* cf = (const float*)d_in[1];
    const float* bw = (const float*)d_in[2];
    const float* pw = (const float*)d_in[3];
    float* out = (float*)d_out;

    MetaAll m;
    build_meta(m);

    precompute_kernel<<<dim3(NGROUPS, 8), 256>>>(cf, bw, pw, m);

    for (int g = 0; g < NGROUPS; ++g) {
        switch (m.cs[g]) {
            case 1:  launch_conv<1 >(x, g, m); break;
            case 2:  launch_conv<2 >(x, g, m); break;
            case 4:  launch_conv<4 >(x, g, m); break;
            case 5:  launch_conv<5 >(x, g, m); break;
            case 8:  launch_conv<8 >(x, g, m); break;
            case 10: launch_conv<10>(x, g, m); break;
            case 16: launch_conv<16>(x, g, m); break;
            case 20: launch_conv<20>(x, g, m); break;
            case 32: launch_conv<32>(x, g, m); break;
            default: launch_conv<40>(x, g, m); break;
        }
    }

    size_t pool_smem = 0;
    for (int g = 0; g < NGROUPS; ++g) {
        size_t s = (size_t)(m.ws[g] * NPERG) * sizeof(float);
        if (s > pool_smem) pool_smem = s;
    }
    int pool_bx = (BATCH * OUT_T + 7) / 8;
    dim3 pool_grid(pool_bx, NGROUPS);
    pool_kernel<<<pool_grid, 256, pool_smem>>>(out, m);
}